// round 14
// baseline (speedup 1.0000x reference)
#include <cuda_runtime.h>
#include <cuda_fp16.h>
#include <cstdint>

#define NPTS 131072
#define K3 27
#define CENTER 13
#define SMEM_BYTES 43776

__device__ __align__(16) char  g_Fs[NPTS*128];      // x_F rows: 32 fp16 hi | 32 fp16 lo
__device__ __align__(16) char  g_Xs[NPTS*128];      // x rows (for conv2)
__device__ __align__(16) char  g_Ws[2][K3*5120];    // per tap: hi[32d x 80B] | lo[32d x 80B]
__device__ __align__(16) float g_x[NPTS*32];
__device__ float g_s[NPTS];
__device__ float g_norm[NPTS];
__device__ unsigned long long g_key[NPTS];
__device__ unsigned char g_mask[NPTS];
__device__ int g_list[NPTS];
__device__ int g_hist[2][4096];
__device__ unsigned long long g_prefix[2];
__device__ int g_remain[2];
__device__ int g_count;
__device__ int g_nbpts;

__device__ __forceinline__ void cpa16(uint32_t d, const void* s, int sz) {
    asm volatile("cp.async.ca.shared.global [%0], [%1], 16, %2;" :: "r"(d), "l"(s), "r"(sz) : "memory");
}
__device__ __forceinline__ void cpac()  { asm volatile("cp.async.commit_group;" ::: "memory"); }
__device__ __forceinline__ void cpaw0() { asm volatile("cp.async.wait_group 0;" ::: "memory"); }
#define LDSM4(R, a) \
    asm volatile("ldmatrix.sync.aligned.m8n8.x4.shared.b16 {%0,%1,%2,%3}, [%4];" \
        : "=r"((R)[0]),"=r"((R)[1]),"=r"((R)[2]),"=r"((R)[3]) : "r"(a))
#define MMA(C, A0,A1,A2,A3, B0,B1) \
    asm volatile("mma.sync.aligned.m16n8k16.row.col.f32.f16.f16.f32 " \
        "{%0,%1,%2,%3},{%4,%5,%6,%7},{%8,%9},{%0,%1,%2,%3};" \
        : "+f"((C)[0]),"+f"((C)[1]),"+f"((C)[2]),"+f"((C)[3]) \
        : "r"(A0),"r"(A1),"r"(A2),"r"(A3),"r"(B0),"r"(B1))

__device__ __forceinline__ uint32_t ph2(float a, float b) {
    __half2 h = __floats2half2_rn(a, b);
    return *(uint32_t*)&h;
}
__device__ __forceinline__ float hlo(float v) { return v - __half2float(__float2half_rn(v)); }
__device__ int dsmall(const int* p, int fb) {
    int v = p[0];
    if (v > 0 && v < (1 << 20)) return v;
    float f = __int_as_float(v);
    if (f >= 1.f && f < 1048576.f && f == floorf(f)) return (int)f;
    return fb;
}

// weight prep + x_F split + select-state reset, fused
__global__ void init_kernel(const float* __restrict__ Wch, const float* __restrict__ Wdw,
                            const float* __restrict__ xF,
                            const int* th_p, const int* nb_p)
{
    int tid = blockIdx.x * blockDim.x + threadIdx.x;
    for (int idx = tid; idx < K3 * 1024; idx += gridDim.x * blockDim.x) {
        int k = idx >> 10, r = idx & 1023, c = r >> 5, d = r & 31;
        #pragma unroll
        for (int s = 0; s < 2; s++) {
            float w = (s ? Wdw[idx] : Wch[idx]) * 1024.f;
            __half whi = __float2half_rn(w);
            __half wlo = __float2half_rn(w - __half2float(whi));
            char* tb = g_Ws[s] + (size_t)k * 5120 + d * 80 + c * 2;
            *(__half*)tb = whi;
            *(__half*)(tb + 2560) = wlo;
        }
    }
    for (int n = tid; n < NPTS; n += gridDim.x * blockDim.x) {
        const float* row = xF + (size_t)n * 32;
        uint32_t hw[16], lw[16];
        #pragma unroll
        for (int i = 0; i < 16; i++) {
            float a = row[2*i], b = row[2*i+1];
            hw[i] = ph2(a, b);
            lw[i] = ph2(hlo(a), hlo(b));
        }
        float4* d = (float4*)(g_Fs + (size_t)n * 128);
        #pragma unroll
        for (int i = 0; i < 4; i++) { d[i] = ((float4*)hw)[i]; d[4+i] = ((float4*)lw)[i]; }
    }
    if (tid == 0) {
        int th = dsmall(th_p, 1), nbb = dsmall(nb_p, 2);
        int nbpts = NPTS / nbb;
        g_nbpts = nbpts;
        int kk = (int)(((double)nbpts * (double)th) / 3.21);
        g_remain[0] = kk; g_remain[1] = kk;
        g_prefix[0] = 0; g_prefix[1] = 0;
        g_count = 0;
    }
    for (int i = tid; i < 8192; i += gridDim.x * blockDim.x) ((int*)g_hist)[i] = 0;
}

// smem (from 128-aligned sA): A 2x16384 | W 2x5120 @32768 | sb @43008 | sPnt @43136
template<bool SECOND>
__global__ void __launch_bounds__(256)
conv_mma(const float* __restrict__ bias, const int* __restrict__ nbr, float* __restrict__ out)
{
    extern __shared__ char sm[];
    const int tid = threadIdx.x, lane = tid & 31;
    const int t0 = blockIdx.x * 128;
    int cnt = 0;
    if (SECOND) { cnt = g_count; if (t0 >= cnt) return; }
    uint32_t base;
    asm("{.reg .u64 t; cvta.to.shared.u64 t, %1; cvt.u32.u64 %0, t;}" : "=r"(base) : "l"(sm));
    const uint32_t sA = (base + 127) & ~127u;
    const uint32_t sW = sA + 32768;
    char* p0 = sm + (sA - base);
    float* sb = (float*)(p0 + 43008);
    int* sPnt = (int*)(p0 + 43136);
    const char* F  = SECOND ? g_Xs : g_Fs;
    const char* Wt = g_Ws[SECOND ? 1 : 0];

    if (tid < 32) sb[tid] = bias[tid];
    if (SECOND && tid < 128) sPnt[tid] = (t0 + tid < cnt) ? g_list[t0 + tid] : -1;
    __syncthreads();

    auto stage = [&](int k, int b) {
        uint32_t Ab = sA + b * 16384;
        #pragma unroll
        for (int j = 0; j < 4; j++) {
            int idx = (j << 8) + tid, pt = idx >> 3, q = idx & 7;
            int n = SECOND ? sPnt[pt] : (t0 + pt);
            int nb = -1;
            if (n >= 0) nb = __ldg(nbr + (size_t)n * K3 + k);
            if (SECOND && nb >= 0 && !g_mask[nb]) nb = -1;
            const char* src = F + ((size_t)(nb < 0 ? 0 : nb) << 7) + (q << 4);
            cpa16(Ab + (pt << 7) + (((q ^ pt) & 7) << 4), src, nb >= 0 ? 16 : 0);
        }
        const char* ws = Wt + (size_t)k * 5120;
        uint32_t Wb = sW + b * 5120;
        cpa16(Wb + tid * 16, ws + tid * 16, 16);
        if (tid < 64) cpa16(Wb + 4096 + tid * 16, ws + 4096 + tid * 16, 16);
    };

    stage(0, 0); cpac(); cpaw0(); __syncthreads();

    float C[4][4];
    #pragma unroll
    for (int i = 0; i < 4; i++) { C[i][0]=0.f; C[i][1]=0.f; C[i][2]=0.f; C[i][3]=0.f; }
    const int wbase = (tid >> 5) * 16;
    const int prow = wbase + (lane >> 2);
    const int acol = (lane & 3) * 2;

    const int ldj = lane >> 3, ldr = lane & 7;
    uint32_t aoff[4];
    {
        int row = wbase + ((ldj & 1) << 3) + ldr;
        #pragma unroll
        for (int t = 0; t < 4; t++) {
            int c = 2 * t + (ldj >> 1);
            aoff[t] = (row << 7) + (((c ^ (row & 7)) & 7) << 4);
        }
    }
    const uint32_t boff = ldr * 80 + ldj * 16;

    for (int k = 0; k < K3; k++) {
        if (k + 1 < K3) { stage(k + 1, (k + 1) & 1); cpac(); }
        const uint32_t Ab = sA + (k & 1) * 16384;
        const uint32_t Wb = sW + (k & 1) * 5120;
        uint32_t A[4][4];                 // 0:hi-ks0 1:hi-ks1 2:lo-ks0 3:lo-ks1
        #pragma unroll
        for (int t = 0; t < 4; t++) LDSM4(A[t], Ab + aoff[t]);
        #pragma unroll
        for (int nt = 0; nt < 4; nt++) {
            uint32_t Bh[4], Bl[4];        // [ks0b0, ks0b1, ks1b0, ks1b1]
            LDSM4(Bh, Wb + nt * 640 + boff);
            LDSM4(Bl, Wb + 2560 + nt * 640 + boff);
            MMA(C[nt], A[0][0],A[0][1],A[0][2],A[0][3], Bh[0],Bh[1]);
            MMA(C[nt], A[0][0],A[0][1],A[0][2],A[0][3], Bl[0],Bl[1]);
            MMA(C[nt], A[2][0],A[2][1],A[2][2],A[2][3], Bh[0],Bh[1]);
            MMA(C[nt], A[1][0],A[1][1],A[1][2],A[1][3], Bh[2],Bh[3]);
            MMA(C[nt], A[1][0],A[1][1],A[1][2],A[1][3], Bl[2],Bl[3]);
            MMA(C[nt], A[3][0],A[3][1],A[3][2],A[3][3], Bh[2],Bh[3]);
        }
        if (k + 1 < K3) { cpaw0(); __syncthreads(); }
    }

    __syncthreads();
    #pragma unroll
    for (int nt = 0; nt < 4; nt++) {
        int n0 = nt * 8 + acol;
        *(float2*)(p0 + prow * 136 + n0 * 4)       = make_float2(C[nt][0], C[nt][1]);
        *(float2*)(p0 + (prow + 8) * 136 + n0 * 4) = make_float2(C[nt][2], C[nt][3]);
    }
    __syncthreads();

    if (tid < 128) {
        int n = SECOND ? sPnt[tid] : (t0 + tid);
        if (!SECOND || n >= 0) {
            const float* cr = (const float*)(p0 + tid * 136);
            float r[32];
            #pragma unroll
            for (int i = 0; i < 32; i++) r[i] = cr[i] * 0.0009765625f + sb[i];
            if (!SECOND) {
                float s = 0.f, nm = 0.f;
                #pragma unroll
                for (int i = 0; i < 32; i++) { s += r[i]; nm += r[i] * r[i]; }
                #pragma unroll
                for (int i = 0; i < 8; i++)
                    *(float4*)(g_x + ((size_t)n << 5) + i * 4) =
                        make_float4(r[4*i], r[4*i+1], r[4*i+2], r[4*i+3]);
                g_s[n] = s; g_norm[n] = nm;
                uint32_t hw[16], lw[16];
                #pragma unroll
                for (int i = 0; i < 16; i++) {
                    hw[i] = ph2(r[2*i], r[2*i+1]);
                    lw[i] = ph2(hlo(r[2*i]), hlo(r[2*i+1]));
                }
                float4* d = (float4*)(g_Xs + ((size_t)n << 7));
                #pragma unroll
                for (int i = 0; i < 4; i++) { d[i] = ((float4*)hw)[i]; d[4+i] = ((float4*)lw)[i]; }
            } else {
                #pragma unroll
                for (int i = 0; i < 8; i++) {
                    float4 xv = *(const float4*)(g_x + ((size_t)n << 5) + i * 4);
                    *(float4*)(out + ((size_t)n << 5) + i * 4) =
                        make_float4(r[4*i] + xv.x, r[4*i+1] + xv.y, r[4*i+2] + xv.z, r[4*i+3] + xv.w);
                }
            }
        }
    }
}

__global__ void corr_kernel(const int* __restrict__ nbr)
{
    int n = blockIdx.x * blockDim.x + threadIdx.x;
    if (n >= NPTS) return;
    const int* row = nbr + (size_t)n * K3;
    float sum = 0.f;
    #pragma unroll
    for (int k = 0; k < K3; k++) {
        if (k == CENTER) continue;
        int nb = row[k];
        if (nb >= 0) sum += __ldg(&g_s[nb]);
    }
    float corr = sum / g_norm[n];
    unsigned u = __float_as_uint(corr);
    u ^= (u & 0x80000000u) ? 0xFFFFFFFFu : 0x80000000u;
    unsigned li = (unsigned)(n % g_nbpts);
    g_key[n] = ((unsigned long long)u << 16) | (unsigned long long)(0xFFFFu - li);
}

// round-1 histogram (bits 47:36) — distributed, as before
__global__ void hist_kernel()
{
    __shared__ int h[4096];
    const int nbpts = g_nbpts;
    const int b = blockIdx.y;
    for (int i = threadIdx.x; i < 4096; i += blockDim.x) h[i] = 0;
    __syncthreads();
    for (int i = blockIdx.x * blockDim.x + threadIdx.x; i < nbpts; i += gridDim.x * blockDim.x) {
        unsigned long long key = g_key[(size_t)b * nbpts + i];
        atomicAdd(&h[(int)((key >> 36) & 4095)], 1);
    }
    __syncthreads();
    for (int i = threadIdx.x; i < 4096; i += blockDim.x) {
        int v = h[i];
        if (v) atomicAdd(&g_hist[b][i], v);
    }
}

// pick round 1, then rounds 2-4 (scan + smem hist + pick) in ONE block per batch
__global__ void __launch_bounds__(1024) select_kernel()
{
    __shared__ int h[4096];
    __shared__ int tsum[256];
    __shared__ int tsuf[257];
    __shared__ unsigned long long s_pref;
    __shared__ int s_rem;
    const int b = blockIdx.x, t = threadIdx.x;
    const int nbpts = g_nbpts;
    const unsigned long long* keys = g_key + (size_t)b * nbpts;
    if (t == 0) { s_pref = 0ull; s_rem = g_remain[b]; }
    __syncthreads();

    for (int round = 0; round < 4; round++) {
        const int shift = 36 - round * 12;
        if (round == 0) {
            // hist already in g_hist[b]; copy into smem
            for (int i = t; i < 4096; i += 1024) h[i] = g_hist[b][i];
            __syncthreads();
        } else {
            for (int i = t; i < 4096; i += 1024) h[i] = 0;
            __syncthreads();
            const unsigned long long pref = s_pref >> (shift + 12);
            for (int i = t * 2; i < nbpts; i += 2048) {
                ulonglong2 kv = *(const ulonglong2*)(keys + i);
                if ((kv.x >> (shift + 12)) == pref)
                    atomicAdd(&h[(int)((kv.x >> shift) & 4095)], 1);
                if ((kv.y >> (shift + 12)) == pref)
                    atomicAdd(&h[(int)((kv.y >> shift) & 4095)], 1);
            }
            __syncthreads();
        }
        const int remain = s_rem;
        if (t < 256) {
            int s = 0;
            #pragma unroll
            for (int i = 0; i < 16; i++) s += h[t * 16 + i];
            tsum[t] = s;
        }
        __syncthreads();
        if (t == 0) {
            int a = 0; tsuf[256] = 0;
            for (int i = 255; i >= 0; --i) { a += tsum[i]; tsuf[i] = a; }
        }
        __syncthreads();
        if (t < 256) {
            int suf = tsuf[t + 1];
            for (int i = 15; i >= 0; --i) {
                int hv = h[t * 16 + i];
                int sn = suf + hv;
                if (sn >= remain && suf < remain) {      // exactly one (t,i) hits
                    s_pref = s_pref | ((unsigned long long)(t * 16 + i) << shift);
                    s_rem = remain - suf;
                }
                suf = sn;
            }
        }
        __syncthreads();
    }
    if (t == 0) g_prefix[b] = s_pref;
}

__global__ void mask_kernel(float* __restrict__ out)
{
    int n = blockIdx.x * blockDim.x + threadIdx.x;
    if (n >= NPTS) return;
    int b = n / g_nbpts;
    bool m = g_key[n] >= g_prefix[b];
    g_mask[n] = m ? 1 : 0;
    if (m) { int pos = atomicAdd(&g_count, 1); g_list[pos] = n; }
    #pragma unroll
    for (int i = 0; i < 8; i++) {
        float4 v = *(const float4*)(g_x + ((size_t)n << 5) + i * 4);
        *(float4*)(out + ((size_t)n << 5) + i * 4) =
            make_float4(v.x + v.x, v.y + v.y, v.z + v.z, v.w + v.w);
    }
}

extern "C" void kernel_launch(void* const* d_in, const int* in_sizes, int n_in,
                              void* d_out, int out_size)
{
    const float* xF  = (const float*)d_in[0];
    const float* Wch = (const float*)d_in[1];
    const float* bch = (const float*)d_in[2];
    const float* Wdw = (const float*)d_in[3];
    const float* bdw = (const float*)d_in[4];
    const int*   nbr = (const int*)d_in[5];
    const int*   th  = (const int*)d_in[6];
    const int*   nbb = (const int*)d_in[7];
    float* out = (float*)d_out;

    cudaFuncSetAttribute(conv_mma<false>, cudaFuncAttributeMaxDynamicSharedMemorySize, SMEM_BYTES);
    cudaFuncSetAttribute(conv_mma<true>,  cudaFuncAttributeMaxDynamicSharedMemorySize, SMEM_BYTES);

    init_kernel<<<148, 256>>>(Wch, Wdw, xF, th, nbb);
    conv_mma<false><<<NPTS / 128, 256, SMEM_BYTES>>>(bch, nbr, out);
    corr_kernel<<<NPTS / 256, 256>>>(nbr);
    hist_kernel<<<dim3(64, 2), 256>>>();
    select_kernel<<<2, 1024>>>();
    mask_kernel<<<NPTS / 256, 256>>>(out);
    conv_mma<true><<<NPTS / 128, 256, SMEM_BYTES>>>(bdw, nbr, out);
}

// round 15
// speedup vs baseline: 1.0859x; 1.0859x over previous
#include <cuda_runtime.h>
#include <cuda_fp16.h>
#include <cstdint>

#define NPTS 131072
#define K3 27
#define CENTER 13
#define SMEM_BYTES 43776

__device__ __align__(16) char  g_Fs[NPTS*128];      // x_F rows: 32 fp16 hi | 32 fp16 lo
__device__ __align__(16) char  g_Xs[NPTS*128];      // x rows (for conv2)
__device__ __align__(16) char  g_Ws[2][K3*5120];    // per tap: hi[32d x 80B] | lo[32d x 80B]
__device__ __align__(16) float g_x[NPTS*32];
__device__ float g_s[NPTS];
__device__ float g_norm[NPTS];
__device__ unsigned long long g_key[NPTS];
__device__ unsigned long long g_cand[2][65536];
__device__ int g_ccount[2];
__device__ unsigned char g_mask[NPTS];
__device__ int g_list[NPTS];
__device__ int g_hist[2][4096];
__device__ unsigned long long g_prefix[2];
__device__ int g_remain[2];
__device__ int g_count;
__device__ int g_nbpts;

__device__ __forceinline__ void cpa16(uint32_t d, const void* s, int sz) {
    asm volatile("cp.async.ca.shared.global [%0], [%1], 16, %2;" :: "r"(d), "l"(s), "r"(sz) : "memory");
}
__device__ __forceinline__ void cpac()  { asm volatile("cp.async.commit_group;" ::: "memory"); }
__device__ __forceinline__ void cpaw0() { asm volatile("cp.async.wait_group 0;" ::: "memory"); }
#define LDSM4(R, a) \
    asm volatile("ldmatrix.sync.aligned.m8n8.x4.shared.b16 {%0,%1,%2,%3}, [%4];" \
        : "=r"((R)[0]),"=r"((R)[1]),"=r"((R)[2]),"=r"((R)[3]) : "r"(a))
#define MMA(C, A0,A1,A2,A3, B0,B1) \
    asm volatile("mma.sync.aligned.m16n8k16.row.col.f32.f16.f16.f32 " \
        "{%0,%1,%2,%3},{%4,%5,%6,%7},{%8,%9},{%0,%1,%2,%3};" \
        : "+f"((C)[0]),"+f"((C)[1]),"+f"((C)[2]),"+f"((C)[3]) \
        : "r"(A0),"r"(A1),"r"(A2),"r"(A3),"r"(B0),"r"(B1))

__device__ __forceinline__ uint32_t ph2(float a, float b) {
    __half2 h = __floats2half2_rn(a, b);
    return *(uint32_t*)&h;
}
__device__ __forceinline__ float hlo(float v) { return v - __half2float(__float2half_rn(v)); }
__device__ int dsmall(const int* p, int fb) {
    int v = p[0];
    if (v > 0 && v < (1 << 20)) return v;
    float f = __int_as_float(v);
    if (f >= 1.f && f < 1048576.f && f == floorf(f)) return (int)f;
    return fb;
}

// weight prep + x_F split + select-state reset, fused
__global__ void init_kernel(const float* __restrict__ Wch, const float* __restrict__ Wdw,
                            const float* __restrict__ xF,
                            const int* th_p, const int* nb_p)
{
    int tid = blockIdx.x * blockDim.x + threadIdx.x;
    for (int idx = tid; idx < K3 * 1024; idx += gridDim.x * blockDim.x) {
        int k = idx >> 10, r = idx & 1023, c = r >> 5, d = r & 31;
        #pragma unroll
        for (int s = 0; s < 2; s++) {
            float w = (s ? Wdw[idx] : Wch[idx]) * 1024.f;
            __half whi = __float2half_rn(w);
            __half wlo = __float2half_rn(w - __half2float(whi));
            char* tb = g_Ws[s] + (size_t)k * 5120 + d * 80 + c * 2;
            *(__half*)tb = whi;
            *(__half*)(tb + 2560) = wlo;
        }
    }
    for (int n = tid; n < NPTS; n += gridDim.x * blockDim.x) {
        const float* row = xF + (size_t)n * 32;
        uint32_t hw[16], lw[16];
        #pragma unroll
        for (int i = 0; i < 16; i++) {
            float a = row[2*i], b = row[2*i+1];
            hw[i] = ph2(a, b);
            lw[i] = ph2(hlo(a), hlo(b));
        }
        float4* d = (float4*)(g_Fs + (size_t)n * 128);
        #pragma unroll
        for (int i = 0; i < 4; i++) { d[i] = ((float4*)hw)[i]; d[4+i] = ((float4*)lw)[i]; }
    }
    if (tid == 0) {
        int th = dsmall(th_p, 1), nbb = dsmall(nb_p, 2);
        int nbpts = NPTS / nbb;
        g_nbpts = nbpts;
        int kk = (int)(((double)nbpts * (double)th) / 3.21);
        g_remain[0] = kk; g_remain[1] = kk;
        g_prefix[0] = 0; g_prefix[1] = 0;
        g_count = 0;
        g_ccount[0] = 0; g_ccount[1] = 0;
    }
    for (int i = tid; i < 8192; i += gridDim.x * blockDim.x) ((int*)g_hist)[i] = 0;
}

// smem (from 128-aligned sA): A 2x16384 | W 2x5120 @32768 | sb @43008 | sPnt @43136
template<bool SECOND>
__global__ void __launch_bounds__(256)
conv_mma(const float* __restrict__ bias, const int* __restrict__ nbr, float* __restrict__ out)
{
    extern __shared__ char sm[];
    const int tid = threadIdx.x, lane = tid & 31;
    const int t0 = blockIdx.x * 128;
    int cnt = 0;
    if (SECOND) { cnt = g_count; if (t0 >= cnt) return; }
    uint32_t base;
    asm("{.reg .u64 t; cvta.to.shared.u64 t, %1; cvt.u32.u64 %0, t;}" : "=r"(base) : "l"(sm));
    const uint32_t sA = (base + 127) & ~127u;
    const uint32_t sW = sA + 32768;
    char* p0 = sm + (sA - base);
    float* sb = (float*)(p0 + 43008);
    int* sPnt = (int*)(p0 + 43136);
    const char* F  = SECOND ? g_Xs : g_Fs;
    const char* Wt = g_Ws[SECOND ? 1 : 0];

    if (tid < 32) sb[tid] = bias[tid];
    if (SECOND && tid < 128) sPnt[tid] = (t0 + tid < cnt) ? g_list[t0 + tid] : -1;
    __syncthreads();

    auto stage = [&](int k, int b) {
        uint32_t Ab = sA + b * 16384;
        #pragma unroll
        for (int j = 0; j < 4; j++) {
            int idx = (j << 8) + tid, pt = idx >> 3, q = idx & 7;
            int n = SECOND ? sPnt[pt] : (t0 + pt);
            int nb = -1;
            if (n >= 0) nb = __ldg(nbr + (size_t)n * K3 + k);
            if (SECOND && nb >= 0 && !g_mask[nb]) nb = -1;
            const char* src = F + ((size_t)(nb < 0 ? 0 : nb) << 7) + (q << 4);
            cpa16(Ab + (pt << 7) + (((q ^ pt) & 7) << 4), src, nb >= 0 ? 16 : 0);
        }
        const char* ws = Wt + (size_t)k * 5120;
        uint32_t Wb = sW + b * 5120;
        cpa16(Wb + tid * 16, ws + tid * 16, 16);
        if (tid < 64) cpa16(Wb + 4096 + tid * 16, ws + 4096 + tid * 16, 16);
    };

    stage(0, 0); cpac(); cpaw0(); __syncthreads();

    float C[4][4];
    #pragma unroll
    for (int i = 0; i < 4; i++) { C[i][0]=0.f; C[i][1]=0.f; C[i][2]=0.f; C[i][3]=0.f; }
    const int wbase = (tid >> 5) * 16;
    const int prow = wbase + (lane >> 2);
    const int acol = (lane & 3) * 2;

    const int ldj = lane >> 3, ldr = lane & 7;
    uint32_t aoff[4];
    {
        int row = wbase + ((ldj & 1) << 3) + ldr;
        #pragma unroll
        for (int t = 0; t < 4; t++) {
            int c = 2 * t + (ldj >> 1);
            aoff[t] = (row << 7) + (((c ^ (row & 7)) & 7) << 4);
        }
    }
    const uint32_t boff = ldr * 80 + ldj * 16;

    for (int k = 0; k < K3; k++) {
        if (k + 1 < K3) { stage(k + 1, (k + 1) & 1); cpac(); }
        const uint32_t Ab = sA + (k & 1) * 16384;
        const uint32_t Wb = sW + (k & 1) * 5120;
        uint32_t A[4][4];                 // 0:hi-ks0 1:hi-ks1 2:lo-ks0 3:lo-ks1
        #pragma unroll
        for (int t = 0; t < 4; t++) LDSM4(A[t], Ab + aoff[t]);
        #pragma unroll
        for (int nt = 0; nt < 4; nt++) {
            uint32_t Bh[4], Bl[4];        // [ks0b0, ks0b1, ks1b0, ks1b1]
            LDSM4(Bh, Wb + nt * 640 + boff);
            LDSM4(Bl, Wb + 2560 + nt * 640 + boff);
            MMA(C[nt], A[0][0],A[0][1],A[0][2],A[0][3], Bh[0],Bh[1]);
            MMA(C[nt], A[0][0],A[0][1],A[0][2],A[0][3], Bl[0],Bl[1]);
            MMA(C[nt], A[2][0],A[2][1],A[2][2],A[2][3], Bh[0],Bh[1]);
            MMA(C[nt], A[1][0],A[1][1],A[1][2],A[1][3], Bh[2],Bh[3]);
            MMA(C[nt], A[1][0],A[1][1],A[1][2],A[1][3], Bl[2],Bl[3]);
            MMA(C[nt], A[3][0],A[3][1],A[3][2],A[3][3], Bh[2],Bh[3]);
        }
        if (k + 1 < K3) { cpaw0(); __syncthreads(); }
    }

    __syncthreads();
    #pragma unroll
    for (int nt = 0; nt < 4; nt++) {
        int n0 = nt * 8 + acol;
        *(float2*)(p0 + prow * 136 + n0 * 4)       = make_float2(C[nt][0], C[nt][1]);
        *(float2*)(p0 + (prow + 8) * 136 + n0 * 4) = make_float2(C[nt][2], C[nt][3]);
    }
    __syncthreads();

    if (tid < 128) {
        int n = SECOND ? sPnt[tid] : (t0 + tid);
        if (!SECOND || n >= 0) {
            const float* cr = (const float*)(p0 + tid * 136);
            float r[32];
            #pragma unroll
            for (int i = 0; i < 32; i++) r[i] = cr[i] * 0.0009765625f + sb[i];
            if (!SECOND) {
                float s = 0.f, nm = 0.f;
                #pragma unroll
                for (int i = 0; i < 32; i++) { s += r[i]; nm += r[i] * r[i]; }
                #pragma unroll
                for (int i = 0; i < 8; i++)
                    *(float4*)(g_x + ((size_t)n << 5) + i * 4) =
                        make_float4(r[4*i], r[4*i+1], r[4*i+2], r[4*i+3]);
                g_s[n] = s; g_norm[n] = nm;
                uint32_t hw[16], lw[16];
                #pragma unroll
                for (int i = 0; i < 16; i++) {
                    hw[i] = ph2(r[2*i], r[2*i+1]);
                    lw[i] = ph2(hlo(r[2*i]), hlo(r[2*i+1]));
                }
                float4* d = (float4*)(g_Xs + ((size_t)n << 7));
                #pragma unroll
                for (int i = 0; i < 4; i++) { d[i] = ((float4*)hw)[i]; d[4+i] = ((float4*)lw)[i]; }
            } else {
                #pragma unroll
                for (int i = 0; i < 8; i++) {
                    float4 xv = *(const float4*)(g_x + ((size_t)n << 5) + i * 4);
                    *(float4*)(out + ((size_t)n << 5) + i * 4) =
                        make_float4(r[4*i] + xv.x, r[4*i+1] + xv.y, r[4*i+2] + xv.z, r[4*i+3] + xv.w);
                }
            }
        }
    }
}

__global__ void corr_kernel(const int* __restrict__ nbr)
{
    int n = blockIdx.x * blockDim.x + threadIdx.x;
    if (n >= NPTS) return;
    const int* row = nbr + (size_t)n * K3;
    float sum = 0.f;
    #pragma unroll
    for (int k = 0; k < K3; k++) {
        if (k == CENTER) continue;
        int nb = row[k];
        if (nb >= 0) sum += __ldg(&g_s[nb]);
    }
    float corr = sum / g_norm[n];
    unsigned u = __float_as_uint(corr);
    u ^= (u & 0x80000000u) ? 0xFFFFFFFFu : 0x80000000u;
    unsigned li = (unsigned)(n % g_nbpts);
    g_key[n] = ((unsigned long long)u << 16) | (unsigned long long)(0xFFFFu - li);
}

// round-1 histogram over bits 47:36
__global__ void hist_kernel()
{
    __shared__ int h[4096];
    const int nbpts = g_nbpts;
    const int b = blockIdx.y;
    for (int i = threadIdx.x; i < 4096; i += blockDim.x) h[i] = 0;
    __syncthreads();
    for (int i = blockIdx.x * blockDim.x + threadIdx.x; i < nbpts; i += gridDim.x * blockDim.x) {
        unsigned long long key = g_key[(size_t)b * nbpts + i];
        atomicAdd(&h[(int)((key >> 36) & 4095)], 1);
    }
    __syncthreads();
    for (int i = threadIdx.x; i < 4096; i += blockDim.x) {
        int v = h[i];
        if (v) atomicAdd(&g_hist[b][i], v);
    }
}

// round-1 pick (digit at bits 47:36)
__global__ void pick_kernel()
{
    __shared__ int tsum[256], tsuf[257];
    const int b = blockIdx.x, t = threadIdx.x;
    const int remain = g_remain[b];
    int loc[16]; int s = 0;
    const int base = t * 16;
    #pragma unroll
    for (int i = 0; i < 16; i++) { loc[i] = g_hist[b][base + i]; s += loc[i]; }
    tsum[t] = s;
    __syncthreads();
    if (t == 0) {
        int a = 0; tsuf[256] = 0;
        for (int i = 255; i >= 0; --i) { a += tsum[i]; tsuf[i] = a; }
    }
    __syncthreads();
    int suf = tsuf[t + 1];
    for (int i = 15; i >= 0; --i) {
        int sn = suf + loc[i];
        if (sn >= remain && suf < remain) {
            g_prefix[b] |= ((unsigned long long)(base + i)) << 36;
            g_remain[b] = remain - suf;
        }
        suf = sn;
    }
}

// compact keys matching the round-1 digit into g_cand
__global__ void compact_kernel()
{
    const int nbpts = g_nbpts;
    const int b = blockIdx.y;
    const unsigned long long pref = g_prefix[b] >> 36;
    for (int i = blockIdx.x * blockDim.x + threadIdx.x; i < nbpts; i += gridDim.x * blockDim.x) {
        unsigned long long key = g_key[(size_t)b * nbpts + i];
        if ((key >> 36) == pref) {
            int pos = atomicAdd(&g_ccount[b], 1);
            g_cand[b][pos] = key;
        }
    }
}

// rounds 2-4 over the compacted candidates, one block per batch
__global__ void __launch_bounds__(1024) select2_kernel()
{
    __shared__ int h[4096];
    __shared__ int tsum[256], tsuf[257];
    __shared__ unsigned long long s_pref;
    __shared__ int s_rem;
    const int b = blockIdx.x, t = threadIdx.x;
    const int cnt = g_ccount[b];
    const unsigned long long* cand = g_cand[b];
    if (t == 0) { s_pref = g_prefix[b]; s_rem = g_remain[b]; }
    __syncthreads();

    for (int round = 0; round < 3; round++) {
        const int shift = 24 - round * 12;
        for (int i = t; i < 4096; i += 1024) h[i] = 0;
        __syncthreads();
        const unsigned long long pref = s_pref >> (shift + 12);
        for (int i = t; i < cnt; i += 1024) {
            unsigned long long k = cand[i];
            if ((k >> (shift + 12)) == pref)
                atomicAdd(&h[(int)((k >> shift) & 4095)], 1);
        }
        __syncthreads();
        const int remain = s_rem;
        if (t < 256) {
            int s = 0;
            #pragma unroll
            for (int i = 0; i < 16; i++) s += h[t * 16 + i];
            tsum[t] = s;
        }
        __syncthreads();
        if (t == 0) {
            int a = 0; tsuf[256] = 0;
            for (int i = 255; i >= 0; --i) { a += tsum[i]; tsuf[i] = a; }
        }
        __syncthreads();
        if (t < 256) {
            int suf = tsuf[t + 1];
            for (int i = 15; i >= 0; --i) {
                int hv = h[t * 16 + i];
                int sn = suf + hv;
                if (sn >= remain && suf < remain) {      // exactly one (t,i) hits
                    s_pref = s_pref | ((unsigned long long)(t * 16 + i) << shift);
                    s_rem = remain - suf;
                }
                suf = sn;
            }
        }
        __syncthreads();
    }
    if (t == 0) g_prefix[b] = s_pref;
}

__global__ void mask_kernel(float* __restrict__ out)
{
    int n = blockIdx.x * blockDim.x + threadIdx.x;
    if (n >= NPTS) return;
    int b = n / g_nbpts;
    bool m = g_key[n] >= g_prefix[b];
    g_mask[n] = m ? 1 : 0;
    if (m) { int pos = atomicAdd(&g_count, 1); g_list[pos] = n; }
    #pragma unroll
    for (int i = 0; i < 8; i++) {
        float4 v = *(const float4*)(g_x + ((size_t)n << 5) + i * 4);
        *(float4*)(out + ((size_t)n << 5) + i * 4) =
            make_float4(v.x + v.x, v.y + v.y, v.z + v.z, v.w + v.w);
    }
}

extern "C" void kernel_launch(void* const* d_in, const int* in_sizes, int n_in,
                              void* d_out, int out_size)
{
    const float* xF  = (const float*)d_in[0];
    const float* Wch = (const float*)d_in[1];
    const float* bch = (const float*)d_in[2];
    const float* Wdw = (const float*)d_in[3];
    const float* bdw = (const float*)d_in[4];
    const int*   nbr = (const int*)d_in[5];
    const int*   th  = (const int*)d_in[6];
    const int*   nbb = (const int*)d_in[7];
    float* out = (float*)d_out;

    cudaFuncSetAttribute(conv_mma<false>, cudaFuncAttributeMaxDynamicSharedMemorySize, SMEM_BYTES);
    cudaFuncSetAttribute(conv_mma<true>,  cudaFuncAttributeMaxDynamicSharedMemorySize, SMEM_BYTES);

    init_kernel<<<148, 256>>>(Wch, Wdw, xF, th, nbb);
    conv_mma<false><<<NPTS / 128, 256, SMEM_BYTES>>>(bch, nbr, out);
    corr_kernel<<<NPTS / 256, 256>>>(nbr);
    hist_kernel<<<dim3(64, 2), 256>>>();
    pick_kernel<<<2, 256>>>();
    compact_kernel<<<dim3(64, 2), 256>>>();
    select2_kernel<<<2, 1024>>>();
    mask_kernel<<<NPTS / 256, 256>>>(out);
    conv_mma<true><<<NPTS / 128, 256, SMEM_BYTES>>>(bdw, nbr, out);
}

// round 16
// speedup vs baseline: 1.1455x; 1.0549x over previous
#include <cuda_runtime.h>
#include <cuda_fp16.h>
#include <cstdint>

#define NPTS 131072
#define K3 27
#define CENTER 13
#define SMEM_BYTES 43776

__device__ __align__(16) char  g_Fs[NPTS*128];      // x_F rows: 32 fp16 hi | 32 fp16 lo
__device__ __align__(16) char  g_Xs[NPTS*128];      // x rows (for conv2 input and +x term)
__device__ __align__(16) char  g_Ws[2][K3*5120];    // per tap: hi[32d x 80B] | lo[32d x 80B]
__device__ float g_s[NPTS];
__device__ float g_norm[NPTS];
__device__ unsigned long long g_key[NPTS];
__device__ unsigned long long g_cand[2][65536];
__device__ int g_ccount[2];
__device__ unsigned char g_mask[NPTS];
__device__ int g_list[NPTS];
__device__ int g_hist[2][4096];
__device__ unsigned long long g_prefix[2];
__device__ int g_remain[2];
__device__ int g_count;
__device__ int g_nbpts;

__device__ __forceinline__ void cpa16(uint32_t d, const void* s, int sz) {
    asm volatile("cp.async.ca.shared.global [%0], [%1], 16, %2;" :: "r"(d), "l"(s), "r"(sz) : "memory");
}
__device__ __forceinline__ void cpac()  { asm volatile("cp.async.commit_group;" ::: "memory"); }
__device__ __forceinline__ void cpaw0() { asm volatile("cp.async.wait_group 0;" ::: "memory"); }
#define LDSM4(R, a) \
    asm volatile("ldmatrix.sync.aligned.m8n8.x4.shared.b16 {%0,%1,%2,%3}, [%4];" \
        : "=r"((R)[0]),"=r"((R)[1]),"=r"((R)[2]),"=r"((R)[3]) : "r"(a))
#define MMA(C, A0,A1,A2,A3, B0,B1) \
    asm volatile("mma.sync.aligned.m16n8k16.row.col.f32.f16.f16.f32 " \
        "{%0,%1,%2,%3},{%4,%5,%6,%7},{%8,%9},{%0,%1,%2,%3};" \
        : "+f"((C)[0]),"+f"((C)[1]),"+f"((C)[2]),"+f"((C)[3]) \
        : "r"(A0),"r"(A1),"r"(A2),"r"(A3),"r"(B0),"r"(B1))

__device__ __forceinline__ uint32_t ph2(float a, float b) {
    __half2 h = __floats2half2_rn(a, b);
    return *(uint32_t*)&h;
}
__device__ __forceinline__ float hlo(float v) { return v - __half2float(__float2half_rn(v)); }
__device__ int dsmall(const int* p, int fb) {
    int v = p[0];
    if (v > 0 && v < (1 << 20)) return v;
    float f = __int_as_float(v);
    if (f >= 1.f && f < 1048576.f && f == floorf(f)) return (int)f;
    return fb;
}

// weight prep + x_F split + select-state reset, fused
__global__ void init_kernel(const float* __restrict__ Wch, const float* __restrict__ Wdw,
                            const float* __restrict__ xF,
                            const int* th_p, const int* nb_p)
{
    int tid = blockIdx.x * blockDim.x + threadIdx.x;
    for (int idx = tid; idx < K3 * 1024; idx += gridDim.x * blockDim.x) {
        int k = idx >> 10, r = idx & 1023, c = r >> 5, d = r & 31;
        #pragma unroll
        for (int s = 0; s < 2; s++) {
            float w = (s ? Wdw[idx] : Wch[idx]) * 1024.f;
            __half whi = __float2half_rn(w);
            __half wlo = __float2half_rn(w - __half2float(whi));
            char* tb = g_Ws[s] + (size_t)k * 5120 + d * 80 + c * 2;
            *(__half*)tb = whi;
            *(__half*)(tb + 2560) = wlo;
        }
    }
    for (int n = tid; n < NPTS; n += gridDim.x * blockDim.x) {
        const float* row = xF + (size_t)n * 32;
        uint32_t hw[16], lw[16];
        #pragma unroll
        for (int i = 0; i < 16; i++) {
            float a = row[2*i], b = row[2*i+1];
            hw[i] = ph2(a, b);
            lw[i] = ph2(hlo(a), hlo(b));
        }
        float4* d = (float4*)(g_Fs + (size_t)n * 128);
        #pragma unroll
        for (int i = 0; i < 4; i++) { d[i] = ((float4*)hw)[i]; d[4+i] = ((float4*)lw)[i]; }
    }
    if (tid == 0) {
        int th = dsmall(th_p, 1), nbb = dsmall(nb_p, 2);
        int nbpts = NPTS / nbb;
        g_nbpts = nbpts;
        int kk = (int)(((double)nbpts * (double)th) / 3.21);
        g_remain[0] = kk; g_remain[1] = kk;
        g_prefix[0] = 0; g_prefix[1] = 0;
        g_count = 0;
        g_ccount[0] = 0; g_ccount[1] = 0;
    }
    for (int i = tid; i < 8192; i += gridDim.x * blockDim.x) ((int*)g_hist)[i] = 0;
}

// smem (from 128-aligned sA): A 2x16384 | W 2x5120 @32768 | sb @43008 | sPnt @43136
template<bool SECOND>
__global__ void __launch_bounds__(256)
conv_mma(const float* __restrict__ bias, const int* __restrict__ nbr, float* __restrict__ out)
{
    extern __shared__ char sm[];
    const int tid = threadIdx.x, lane = tid & 31;
    const int t0 = blockIdx.x * 128;
    int cnt = 0;
    if (SECOND) { cnt = g_count; if (t0 >= cnt) return; }
    uint32_t base;
    asm("{.reg .u64 t; cvta.to.shared.u64 t, %1; cvt.u32.u64 %0, t;}" : "=r"(base) : "l"(sm));
    const uint32_t sA = (base + 127) & ~127u;
    const uint32_t sW = sA + 32768;
    char* p0 = sm + (sA - base);
    float* sb = (float*)(p0 + 43008);
    int* sPnt = (int*)(p0 + 43136);
    const char* F  = SECOND ? g_Xs : g_Fs;
    const char* Wt = g_Ws[SECOND ? 1 : 0];

    if (tid < 32) sb[tid] = bias[tid];
    if (SECOND && tid < 128) sPnt[tid] = (t0 + tid < cnt) ? g_list[t0 + tid] : -1;
    __syncthreads();

    auto stage = [&](int k, int b) {
        uint32_t Ab = sA + b * 16384;
        #pragma unroll
        for (int j = 0; j < 4; j++) {
            int idx = (j << 8) + tid, pt = idx >> 3, q = idx & 7;
            int n = SECOND ? sPnt[pt] : (t0 + pt);
            int nb = -1;
            if (n >= 0) nb = __ldg(nbr + (size_t)n * K3 + k);
            if (SECOND && nb >= 0 && !g_mask[nb]) nb = -1;
            const char* src = F + ((size_t)(nb < 0 ? 0 : nb) << 7) + (q << 4);
            cpa16(Ab + (pt << 7) + (((q ^ pt) & 7) << 4), src, nb >= 0 ? 16 : 0);
        }
        const char* ws = Wt + (size_t)k * 5120;
        uint32_t Wb = sW + b * 5120;
        cpa16(Wb + tid * 16, ws + tid * 16, 16);
        if (tid < 64) cpa16(Wb + 4096 + tid * 16, ws + 4096 + tid * 16, 16);
    };

    stage(0, 0); cpac(); cpaw0(); __syncthreads();

    float C[4][4];
    #pragma unroll
    for (int i = 0; i < 4; i++) { C[i][0]=0.f; C[i][1]=0.f; C[i][2]=0.f; C[i][3]=0.f; }
    const int wbase = (tid >> 5) * 16;
    const int prow = wbase + (lane >> 2);
    const int acol = (lane & 3) * 2;

    const int ldj = lane >> 3, ldr = lane & 7;
    uint32_t aoff[4];
    {
        int row = wbase + ((ldj & 1) << 3) + ldr;
        #pragma unroll
        for (int t = 0; t < 4; t++) {
            int c = 2 * t + (ldj >> 1);
            aoff[t] = (row << 7) + (((c ^ (row & 7)) & 7) << 4);
        }
    }
    const uint32_t boff = ldr * 80 + ldj * 16;

    for (int k = 0; k < K3; k++) {
        if (k + 1 < K3) { stage(k + 1, (k + 1) & 1); cpac(); }
        const uint32_t Ab = sA + (k & 1) * 16384;
        const uint32_t Wb = sW + (k & 1) * 5120;
        uint32_t A[4][4];                 // 0:hi-ks0 1:hi-ks1 2:lo-ks0 3:lo-ks1
        #pragma unroll
        for (int t = 0; t < 4; t++) LDSM4(A[t], Ab + aoff[t]);
        #pragma unroll
        for (int nt = 0; nt < 4; nt++) {
            uint32_t Bh[4], Bl[4];        // [ks0b0, ks0b1, ks1b0, ks1b1]
            LDSM4(Bh, Wb + nt * 640 + boff);
            LDSM4(Bl, Wb + 2560 + nt * 640 + boff);
            MMA(C[nt], A[0][0],A[0][1],A[0][2],A[0][3], Bh[0],Bh[1]);
            MMA(C[nt], A[0][0],A[0][1],A[0][2],A[0][3], Bl[0],Bl[1]);
            MMA(C[nt], A[2][0],A[2][1],A[2][2],A[2][3], Bh[0],Bh[1]);
            MMA(C[nt], A[1][0],A[1][1],A[1][2],A[1][3], Bh[2],Bh[3]);
            MMA(C[nt], A[1][0],A[1][1],A[1][2],A[1][3], Bl[2],Bl[3]);
            MMA(C[nt], A[3][0],A[3][1],A[3][2],A[3][3], Bh[2],Bh[3]);
        }
        if (k + 1 < K3) { cpaw0(); __syncthreads(); }
    }

    __syncthreads();
    #pragma unroll
    for (int nt = 0; nt < 4; nt++) {
        int n0 = nt * 8 + acol;
        *(float2*)(p0 + prow * 136 + n0 * 4)       = make_float2(C[nt][0], C[nt][1]);
        *(float2*)(p0 + (prow + 8) * 136 + n0 * 4) = make_float2(C[nt][2], C[nt][3]);
    }
    __syncthreads();

    if (tid < 128) {
        int n = SECOND ? sPnt[tid] : (t0 + tid);
        if (!SECOND || n >= 0) {
            const float* cr = (const float*)(p0 + tid * 136);
            float r[32];
            #pragma unroll
            for (int i = 0; i < 32; i++) r[i] = cr[i] * 0.0009765625f + sb[i];
            if (!SECOND) {
                float s = 0.f, nm = 0.f;
                #pragma unroll
                for (int i = 0; i < 32; i++) { s += r[i]; nm += r[i] * r[i]; }
                g_s[n] = s; g_norm[n] = nm;
                // out = 2x baseline (masked rows later overwritten by conv2)
                #pragma unroll
                for (int i = 0; i < 8; i++)
                    *(float4*)(out + ((size_t)n << 5) + i * 4) =
                        make_float4(r[4*i]+r[4*i], r[4*i+1]+r[4*i+1],
                                    r[4*i+2]+r[4*i+2], r[4*i+3]+r[4*i+3]);
                uint32_t hw[16], lw[16];
                #pragma unroll
                for (int i = 0; i < 16; i++) {
                    hw[i] = ph2(r[2*i], r[2*i+1]);
                    lw[i] = ph2(hlo(r[2*i]), hlo(r[2*i+1]));
                }
                float4* d = (float4*)(g_Xs + ((size_t)n << 7));
                #pragma unroll
                for (int i = 0; i < 4; i++) { d[i] = ((float4*)hw)[i]; d[4+i] = ((float4*)lw)[i]; }
            } else {
                // +x term reconstructed from hi+lo (error ~2^-22 relative)
                const uint32_t* xr = (const uint32_t*)(g_Xs + ((size_t)n << 7));
                #pragma unroll
                for (int i = 0; i < 8; i++) {
                    float4 ov;
                    float* o = (float*)&ov;
                    #pragma unroll
                    for (int j = 0; j < 2; j++) {
                        int w = i * 2 + j;
                        float2 h = __half22float2(*(const __half2*)&xr[w]);
                        float2 l = __half22float2(*(const __half2*)&xr[16 + w]);
                        o[2*j]   = r[4*i + 2*j]   + h.x + l.x;
                        o[2*j+1] = r[4*i + 2*j+1] + h.y + l.y;
                    }
                    *(float4*)(out + ((size_t)n << 5) + i * 4) = ov;
                }
            }
        }
    }
}

__global__ void corr_kernel(const int* __restrict__ nbr)
{
    int n = blockIdx.x * blockDim.x + threadIdx.x;
    if (n >= NPTS) return;
    const int* row = nbr + (size_t)n * K3;
    float sum = 0.f;
    #pragma unroll
    for (int k = 0; k < K3; k++) {
        if (k == CENTER) continue;
        int nb = row[k];
        if (nb >= 0) sum += __ldg(&g_s[nb]);
    }
    float corr = sum / g_norm[n];
    unsigned u = __float_as_uint(corr);
    u ^= (u & 0x80000000u) ? 0xFFFFFFFFu : 0x80000000u;
    unsigned li = (unsigned)(n % g_nbpts);
    g_key[n] = ((unsigned long long)u << 16) | (unsigned long long)(0xFFFFu - li);
}

// round-1 histogram over bits 47:36
__global__ void hist_kernel()
{
    __shared__ int h[4096];
    const int nbpts = g_nbpts;
    const int b = blockIdx.y;
    for (int i = threadIdx.x; i < 4096; i += blockDim.x) h[i] = 0;
    __syncthreads();
    for (int i = blockIdx.x * blockDim.x + threadIdx.x; i < nbpts; i += gridDim.x * blockDim.x) {
        unsigned long long key = g_key[(size_t)b * nbpts + i];
        atomicAdd(&h[(int)((key >> 36) & 4095)], 1);
    }
    __syncthreads();
    for (int i = threadIdx.x; i < 4096; i += blockDim.x) {
        int v = h[i];
        if (v) atomicAdd(&g_hist[b][i], v);
    }
}

// round-1 pick (digit at bits 47:36)
__global__ void pick_kernel()
{
    __shared__ int tsum[256], tsuf[257];
    const int b = blockIdx.x, t = threadIdx.x;
    const int remain = g_remain[b];
    int loc[16]; int s = 0;
    const int base = t * 16;
    #pragma unroll
    for (int i = 0; i < 16; i++) { loc[i] = g_hist[b][base + i]; s += loc[i]; }
    tsum[t] = s;
    __syncthreads();
    if (t == 0) {
        int a = 0; tsuf[256] = 0;
        for (int i = 255; i >= 0; --i) { a += tsum[i]; tsuf[i] = a; }
    }
    __syncthreads();
    int suf = tsuf[t + 1];
    for (int i = 15; i >= 0; --i) {
        int sn = suf + loc[i];
        if (sn >= remain && suf < remain) {
            g_prefix[b] |= ((unsigned long long)(base + i)) << 36;
            g_remain[b] = remain - suf;
        }
        suf = sn;
    }
}

// compact keys matching the round-1 digit into g_cand
__global__ void compact_kernel()
{
    const int nbpts = g_nbpts;
    const int b = blockIdx.y;
    const unsigned long long pref = g_prefix[b] >> 36;
    for (int i = blockIdx.x * blockDim.x + threadIdx.x; i < nbpts; i += gridDim.x * blockDim.x) {
        unsigned long long key = g_key[(size_t)b * nbpts + i];
        if ((key >> 36) == pref) {
            int pos = atomicAdd(&g_ccount[b], 1);
            g_cand[b][pos] = key;
        }
    }
}

// rounds 2-4 over the compacted candidates, one block per batch
__global__ void __launch_bounds__(1024) select2_kernel()
{
    __shared__ int h[4096];
    __shared__ int tsum[256], tsuf[257];
    __shared__ unsigned long long s_pref;
    __shared__ int s_rem;
    const int b = blockIdx.x, t = threadIdx.x;
    const int cnt = g_ccount[b];
    const unsigned long long* cand = g_cand[b];
    if (t == 0) { s_pref = g_prefix[b]; s_rem = g_remain[b]; }
    __syncthreads();

    for (int round = 0; round < 3; round++) {
        const int shift = 24 - round * 12;
        for (int i = t; i < 4096; i += 1024) h[i] = 0;
        __syncthreads();
        const unsigned long long pref = s_pref >> (shift + 12);
        for (int i = t; i < cnt; i += 1024) {
            unsigned long long k = cand[i];
            if ((k >> (shift + 12)) == pref)
                atomicAdd(&h[(int)((k >> shift) & 4095)], 1);
        }
        __syncthreads();
        const int remain = s_rem;
        if (t < 256) {
            int s = 0;
            #pragma unroll
            for (int i = 0; i < 16; i++) s += h[t * 16 + i];
            tsum[t] = s;
        }
        __syncthreads();
        if (t == 0) {
            int a = 0; tsuf[256] = 0;
            for (int i = 255; i >= 0; --i) { a += tsum[i]; tsuf[i] = a; }
        }
        __syncthreads();
        if (t < 256) {
            int suf = tsuf[t + 1];
            for (int i = 15; i >= 0; --i) {
                int hv = h[t * 16 + i];
                int sn = suf + hv;
                if (sn >= remain && suf < remain) {
                    s_pref = s_pref | ((unsigned long long)(t * 16 + i) << shift);
                    s_rem = remain - suf;
                }
                suf = sn;
            }
        }
        __syncthreads();
    }
    if (t == 0) g_prefix[b] = s_pref;
}

// mask + compaction only (out baseline already written by conv1)
__global__ void mask_kernel()
{
    int n = blockIdx.x * blockDim.x + threadIdx.x;
    if (n >= NPTS) return;
    int b = n / g_nbpts;
    bool m = g_key[n] >= g_prefix[b];
    g_mask[n] = m ? 1 : 0;
    if (m) { int pos = atomicAdd(&g_count, 1); g_list[pos] = n; }
}

extern "C" void kernel_launch(void* const* d_in, const int* in_sizes, int n_in,
                              void* d_out, int out_size)
{
    const float* xF  = (const float*)d_in[0];
    const float* Wch = (const float*)d_in[1];
    const float* bch = (const float*)d_in[2];
    const float* Wdw = (const float*)d_in[3];
    const float* bdw = (const float*)d_in[4];
    const int*   nbr = (const int*)d_in[5];
    const int*   th  = (const int*)d_in[6];
    const int*   nbb = (const int*)d_in[7];
    float* out = (float*)d_out;

    cudaFuncSetAttribute(conv_mma<false>, cudaFuncAttributeMaxDynamicSharedMemorySize, SMEM_BYTES);
    cudaFuncSetAttribute(conv_mma<true>,  cudaFuncAttributeMaxDynamicSharedMemorySize, SMEM_BYTES);

    init_kernel<<<148, 256>>>(Wch, Wdw, xF, th, nbb);
    conv_mma<false><<<NPTS / 128, 256, SMEM_BYTES>>>(bch, nbr, out);
    corr_kernel<<<NPTS / 256, 256>>>(nbr);
    hist_kernel<<<dim3(64, 2), 256>>>();
    pick_kernel<<<2, 256>>>();
    compact_kernel<<<dim3(64, 2), 256>>>();
    select2_kernel<<<2, 1024>>>();
    mask_kernel<<<NPTS / 256, 256>>>();
    conv_mma<true><<<NPTS / 128, 256, SMEM_BYTES>>>(bdw, nbr, out);
}